// round 15
// baseline (speedup 1.0000x reference)
#include <cuda_runtime.h>
#include <cuda_fp16.h>
#include <cstdint>

#define NNODES 50000
#define DDIM 128
#define NH 8
#define HDIM 16
#define FDIM 512
#define E0 800000
#define ETOT 850000
#define EPS_BN 1e-5f
#define NCHUNK 49   // ceil(50000/1024)

// ---------------- scratch (device globals; no allocation allowed) ----------
__device__ __align__(16) __half g_qh[NNODES * DDIM];
__device__ __align__(16) __half g_kh[NNODES * DDIM];
__device__ __align__(16) __half g_vh[NNODES * DDIM];
__device__ __align__(16) __half g_aggt[NNODES * DDIM];
__device__ __align__(16) float  g_x1[NNODES * DDIM];
__device__ __align__(16) __half g_x1t[NNODES * DDIM];
__device__ __align__(16) float  g_tmp[NNODES * DDIM];
__device__ __align__(16) __half g_ff1t[(size_t)NNODES * FDIM];
__device__ __align__(16) __half g_srct[NNODES * DDIM];
__device__ __align__(16) __half g_wt[196608];
__device__ __align__(16) float  g_stats[512];
__device__ int g_src[ETOT];
__device__ int g_dst[ETOT];
__device__ int g_csr[ETOT];
__device__ int g_deg[NNODES];
__device__ int g_rowptr[NNODES + 1];
__device__ int g_cursor[NNODES];
__device__ int g_csum[64];
__device__ int g_is64;

#define WQ_OFF 0
#define WK_OFF 16384
#define WV_OFF 32768
#define WO_OFF 49152
#define W1_OFF 65536
#define W2_OFF 131072
#define NSRC (NNODES * DDIM)
#define NCONV (NSRC + 196608)

// ---------------- convert + prep (merged): fp16 convert, detect, zero -------
__global__ void convert_kernel(const float* __restrict__ src,
                               const float* __restrict__ wq,
                               const float* __restrict__ wk,
                               const float* __restrict__ wv,
                               const float* __restrict__ wo,
                               const float* __restrict__ w1,
                               const float* __restrict__ w2,
                               const unsigned int* __restrict__ ew) {
    int i = blockIdx.x * blockDim.x + threadIdx.x;
    if (i == 0) {
        int nz = 0;
        for (int j = 1; j < 256; j += 2) nz += (ew[j] != 0u);
        g_is64 = (nz == 0) ? 1 : 0;
    }
    if (i < NNODES) g_deg[i] = 0;
    if (i < 512) g_stats[i] = 0.f;
    int stride = gridDim.x * blockDim.x;
    for (int t = i; t < NCONV; t += stride) {
        if (t < NSRC) {
            g_srct[t] = __float2half_rn(src[t]);
        } else {
            int j = t - NSRC;
            float v;
            if (j < WK_OFF)      v = wq[j - WQ_OFF];
            else if (j < WV_OFF) v = wk[j - WK_OFF];
            else if (j < WO_OFF) v = wv[j - WV_OFF];
            else if (j < W1_OFF) v = wo[j - WO_OFF];
            else if (j < W2_OFF) v = w1[j - W1_OFF];
            else                 v = w2[j - W2_OFF];
            g_wt[j] = __float2half_rn(v);
        }
    }
}

// ---------------- decode edges + degree histogram ---------------------------
__global__ void decode_kernel(const unsigned int* __restrict__ w) {
    int e = blockIdx.x * blockDim.x + threadIdx.x;
    if (e >= ETOT) return;
    int s, d;
    if (e < E0) {
        if (g_is64) {
            s = (int)w[2 * (size_t)e];
            d = (int)w[2 * ((size_t)E0 + e)];
        } else {
            s = (int)w[e];
            d = (int)w[E0 + e];
        }
    } else {
        s = d = e - E0;
    }
    g_src[e] = s;
    g_dst[e] = d;
    atomicAdd(&g_deg[d], 1);
}

// ---------------- CSR build --------------------------------------------------
__global__ void scan1_kernel() {
    __shared__ int sh[1024];
    int t = threadIdx.x;
    int i = blockIdx.x * 1024 + t;
    int v = (i < NNODES) ? g_deg[i] : 0;
    sh[t] = v;
    __syncthreads();
    for (int off = 1; off < 1024; off <<= 1) {
        int x = (t >= off) ? sh[t - off] : 0;
        __syncthreads();
        sh[t] += x;
        __syncthreads();
    }
    if (i < NNODES) g_rowptr[i] = sh[t] - v;
    if (t == 1023) g_csum[blockIdx.x] = sh[1023];
}

__global__ void scan3_kernel() {
    __shared__ int pref;
    if (threadIdx.x == 0) {
        int c = (blockIdx.x * 256) >> 10;
        int run = 0;
        for (int j = 0; j < c; j++) run += g_csum[j];
        pref = run;
    }
    __syncthreads();
    int i = blockIdx.x * blockDim.x + threadIdx.x;
    if (i < NNODES) {
        int rp = g_rowptr[i] + pref;
        g_rowptr[i] = rp;
        g_cursor[i] = rp;
    }
    if (i == 0) g_rowptr[NNODES] = ETOT;
}

__global__ void scatter_kernel() {
    int e = blockIdx.x * blockDim.x + threadIdx.x;
    if (e >= ETOT) return;
    int pos = atomicAdd(&g_cursor[g_dst[e]], 1);
    g_csr[pos] = g_src[e];
}

// ---------------- FP16 tensor-core GEMM (m16n8k16 + ldmatrix) ---------------
#define GM 128
#define GN 128
#define KT 32
#define SK 20
#define BUFB (GM * SK * 4)

__device__ __forceinline__ void mma16(float c[4],
                                      unsigned a0, unsigned a1, unsigned a2, unsigned a3,
                                      unsigned b0, unsigned b1) {
    asm volatile(
        "mma.sync.aligned.m16n8k16.row.col.f32.f16.f16.f32 "
        "{%0,%1,%2,%3}, {%4,%5,%6,%7}, {%8,%9}, {%0,%1,%2,%3};"
        : "+f"(c[0]), "+f"(c[1]), "+f"(c[2]), "+f"(c[3])
        : "r"(a0), "r"(a1), "r"(a2), "r"(a3), "r"(b0), "r"(b1));
}

#define LDSM4(r0, r1, r2, r3, addr) \
    asm volatile("ldmatrix.sync.aligned.m8n8.x4.shared.b16 {%0,%1,%2,%3}, [%4];" \
                 : "=r"(r0), "=r"(r1), "=r"(r2), "=r"(r3) : "r"(addr))

__device__ __forceinline__ float2 lrelu2(float2 o, int act) {
    if (act) {
        o.x = o.x > 0.f ? o.x : 0.01f * o.x;
        o.y = o.y > 0.f ? o.y : 0.01f * o.y;
    }
    return o;
}

__device__ __forceinline__ void gemm_body(
    const __half* __restrict__ A, const __half* __restrict__ B,
    const float* __restrict__ bias, const float* __restrict__ res,
    float* __restrict__ C, __half* __restrict__ Ct,
    int M, int Nn, int K, float alpha, int act, int stats_off,
    int bm, int bn)
{
    __shared__ __align__(16) unsigned As[2][GM][SK];
    __shared__ __align__(16) unsigned Bs[2][GN][SK];
    int tid = threadIdx.x;
    int warp = tid >> 5, lane = tid & 31;
    int wm = warp >> 2, wn = warp & 3;
    int gid = lane >> 2, ctg = lane & 3;
    int lg = lane >> 3, l8 = lane & 7;

    int lrow = tid & 127;
    int kh = (tid >> 7) * 8;
    int kw = K >> 1;
    const unsigned* Ap = (const unsigned*)A + (size_t)(bm + lrow) * kw + kh;
    const unsigned* Bp = (const unsigned*)B + (size_t)(bn + lrow) * kw + kh;
    bool aok = (bm + lrow) < M;

    unsigned sA = (unsigned)__cvta_generic_to_shared(&As[0][0][0]);
    unsigned sB = (unsigned)__cvta_generic_to_shared(&Bs[0][0][0]);
    unsigned aBase = sA + (unsigned)((wm * 64 + (lg & 1) * 8 + l8) * (SK * 4)
                                     + (lg >> 1) * 16);
    unsigned bBase = sB + (unsigned)((wn * 32 + (lg >> 1) * 8 + l8) * (SK * 4)
                                     + (lg & 1) * 16);

    float c[4][4][4];
#pragma unroll
    for (int mt = 0; mt < 4; mt++)
#pragma unroll
        for (int nt = 0; nt < 4; nt++)
#pragma unroll
            for (int r = 0; r < 4; r++) c[mt][nt][r] = 0.f;

    const uint4 z4 = make_uint4(0u, 0u, 0u, 0u);
    uint4 a0v = aok ? *(const uint4*)Ap : z4;
    uint4 a1v = aok ? *(const uint4*)(Ap + 4) : z4;
    uint4 b0v = *(const uint4*)Bp;
    uint4 b1v = *(const uint4*)(Bp + 4);
    *(uint4*)&As[0][lrow][kh]     = a0v;
    *(uint4*)&As[0][lrow][kh + 4] = a1v;
    *(uint4*)&Bs[0][lrow][kh]     = b0v;
    *(uint4*)&Bs[0][lrow][kh + 4] = b1v;
    __syncthreads();

    int nk = K / KT;
    for (int kt = 0; kt < nk; kt++) {
        int cur = kt & 1;
        int nxt = cur ^ 1;
        bool more = (kt + 1) < nk;
        if (more) {
            int off = (kt + 1) * 16;
            a0v = aok ? *(const uint4*)(Ap + off) : z4;
            a1v = aok ? *(const uint4*)(Ap + off + 4) : z4;
            b0v = *(const uint4*)(Bp + off);
            b1v = *(const uint4*)(Bp + off + 4);
        }
        unsigned aB = aBase + cur * BUFB;
        unsigned bB = bBase + cur * BUFB;
#pragma unroll
        for (int ks = 0; ks < 2; ks++) {
            unsigned ksoff = ks * 32;
            unsigned af[4][4], bf[4][2];
#pragma unroll
            for (int mt = 0; mt < 4; mt++)
                LDSM4(af[mt][0], af[mt][1], af[mt][2], af[mt][3],
                      aB + mt * (16 * SK * 4) + ksoff);
#pragma unroll
            for (int np = 0; np < 2; np++)
                LDSM4(bf[np * 2][0], bf[np * 2][1], bf[np * 2 + 1][0],
                      bf[np * 2 + 1][1], bB + np * (16 * SK * 4) + ksoff);
#pragma unroll
            for (int mt = 0; mt < 4; mt++)
#pragma unroll
                for (int nt = 0; nt < 4; nt++)
                    mma16(c[mt][nt], af[mt][0], af[mt][1], af[mt][2], af[mt][3],
                          bf[nt][0], bf[nt][1]);
        }
        if (more) {
            *(uint4*)&As[nxt][lrow][kh]     = a0v;
            *(uint4*)&As[nxt][lrow][kh + 4] = a1v;
            *(uint4*)&Bs[nxt][lrow][kh]     = b0v;
            *(uint4*)&Bs[nxt][lrow][kh + 4] = b1v;
            __syncthreads();
        }
    }

    float ssum[4][2] = {}, ssq[4][2] = {};
#pragma unroll
    for (int nt = 0; nt < 4; nt++) {
        int col = bn + wn * 32 + nt * 8 + 2 * ctg;
        float2 bb = make_float2(0.f, 0.f);
        if (bias) bb = *(const float2*)(bias + col);
#pragma unroll
        for (int mt = 0; mt < 4; mt++) {
            int r0 = bm + wm * 64 + mt * 16 + gid;
            int r1 = r0 + 8;
            if (r0 < M) {
                float2 rv = res ? *(const float2*)(res + (size_t)r0 * Nn + col)
                                : make_float2(0.f, 0.f);
                float2 o;
                o.x = (c[mt][nt][0] + bb.x) * alpha + rv.x;
                o.y = (c[mt][nt][1] + bb.y) * alpha + rv.y;
                o = lrelu2(o, act);
                if (C) *(float2*)(C + (size_t)r0 * Nn + col) = o;
                if (Ct) *(__half2*)(Ct + (size_t)r0 * Nn + col) =
                            __floats2half2_rn(o.x, o.y);
                ssum[nt][0] += o.x; ssum[nt][1] += o.y;
                ssq[nt][0] += o.x * o.x; ssq[nt][1] += o.y * o.y;
            }
            if (r1 < M) {
                float2 rv = res ? *(const float2*)(res + (size_t)r1 * Nn + col)
                                : make_float2(0.f, 0.f);
                float2 o;
                o.x = (c[mt][nt][2] + bb.x) * alpha + rv.x;
                o.y = (c[mt][nt][3] + bb.y) * alpha + rv.y;
                o = lrelu2(o, act);
                if (C) *(float2*)(C + (size_t)r1 * Nn + col) = o;
                if (Ct) *(__half2*)(Ct + (size_t)r1 * Nn + col) =
                            __floats2half2_rn(o.x, o.y);
                ssum[nt][0] += o.x; ssum[nt][1] += o.y;
                ssq[nt][0] += o.x * o.x; ssq[nt][1] += o.y * o.y;
            }
        }
    }

    if (stats_off >= 0) {
        __syncthreads();
        float* sh = (float*)&As[0][0][0];
        sh[tid] = 0.f;
        __syncthreads();
#pragma unroll
        for (int nt = 0; nt < 4; nt++) {
            int cl = wn * 32 + nt * 8 + 2 * ctg;
            atomicAdd(&sh[cl], ssum[nt][0]);
            atomicAdd(&sh[cl + 1], ssum[nt][1]);
            atomicAdd(&sh[128 + cl], ssq[nt][0]);
            atomicAdd(&sh[128 + cl + 1], ssq[nt][1]);
        }
        __syncthreads();
        atomicAdd(&g_stats[stats_off + tid], sh[tid]);
    }
}

__global__ __launch_bounds__(256, 2) void gemm_kernel(
    const __half* __restrict__ A, const __half* __restrict__ B,
    const float* __restrict__ bias, const float* __restrict__ res,
    float* __restrict__ C, __half* __restrict__ Ct,
    int M, int Nn, int K, float alpha, int act, int stats_off)
{
    gemm_body(A, B, bias, res, C, Ct, M, Nn, K, alpha, act, stats_off,
              blockIdx.y * GM, blockIdx.x * GN);
}

__global__ __launch_bounds__(256, 2) void qkv_gemm_kernel(const float* __restrict__ qb) {
    int z = blockIdx.z;
    const __half* B = g_wt + ((z == 0) ? WQ_OFF : (z == 1) ? WK_OFF : WV_OFF);
    __half* Ct = (z == 0) ? g_qh : (z == 1) ? g_kh : g_vh;
    const float* bias = (z == 0) ? qb : nullptr;
    float alpha = (z == 0) ? 0.25f : 1.0f;
    gemm_body(g_srct, B, bias, nullptr, nullptr, Ct,
              NNODES, DDIM, DDIM, alpha, 0, -1, blockIdx.y * GM, 0);
}

// ---------------- CSR attention aggregation: TWO warps per node -------------
// Warp pair (2n, 2n+1) splits node n's neighbor list; partials combined via
// padded smem (stride 5 -> conflict-free). fp16 gathers, deduped exp.
__global__ void node_agg_kernel() {
    int tid = threadIdx.x;
    int wid = tid >> 5;          // 0..7
    int lane = tid & 31;
    int pair = wid >> 1;         // 0..3 node slot within block
    int half = wid & 1;
    int node = blockIdx.x * 4 + pair;
    bool valid = node < NNODES;

    __shared__ float s_part[4][32][5];

    float4 acc = make_float4(0.f, 0.f, 0.f, 0.f);
    float den = 0.f;
    float2 qf0 = make_float2(0.f, 0.f), qf1 = make_float2(0.f, 0.f);

    if (valid) {
        uint2 qa = *((const uint2*)(g_qh + (size_t)node * DDIM) + lane);
        qf0 = __half22float2(*(__half2*)&qa.x);
        qf1 = __half22float2(*(__half2*)&qa.y);
        int beg = g_rowptr[node], end = g_rowptr[node + 1];
        int cnt = end - beg;
        int c0 = (cnt + 1) >> 1;
        int wb = beg + (half ? c0 : 0);
        int we = half ? end : (beg + c0);
        int esel = lane & 3;
        int gbase = lane & ~3;
        int i = wb;
        for (; i + 4 <= we; i += 4) {
            int sv = (lane < 4) ? g_csr[i + lane] : 0;
            int s[4];
#pragma unroll
            for (int j = 0; j < 4; j++) s[j] = __shfl_sync(0xffffffffu, sv, j);
            uint2 kr[4], vr[4];
#pragma unroll
            for (int j = 0; j < 4; j++)
                kr[j] = *((const uint2*)(g_kh + (size_t)s[j] * DDIM) + lane);
#pragma unroll
            for (int j = 0; j < 4; j++)
                vr[j] = *((const uint2*)(g_vh + (size_t)s[j] * DDIM) + lane);
            float p[4];
#pragma unroll
            for (int j = 0; j < 4; j++) {
                float2 k0 = __half22float2(*(__half2*)&kr[j].x);
                float2 k1 = __half22float2(*(__half2*)&kr[j].y);
                p[j] = k0.x * qf0.x + k0.y * qf0.y + k1.x * qf1.x + k1.y * qf1.y;
                p[j] += __shfl_xor_sync(0xffffffffu, p[j], 1);
                p[j] += __shfl_xor_sync(0xffffffffu, p[j], 2);
            }
            float eo = __expf(esel == 0 ? p[0] : esel == 1 ? p[1]
                              : esel == 2 ? p[2] : p[3]);
            float e[4];
#pragma unroll
            for (int j = 0; j < 4; j++)
                e[j] = __shfl_sync(0xffffffffu, eo, gbase + j);
#pragma unroll
            for (int j = 0; j < 4; j++) {
                den += e[j];
                float2 v0 = __half22float2(*(__half2*)&vr[j].x);
                float2 v1 = __half22float2(*(__half2*)&vr[j].y);
                acc.x += e[j] * v0.x; acc.y += e[j] * v0.y;
                acc.z += e[j] * v1.x; acc.w += e[j] * v1.y;
            }
        }
        for (; i < we; i++) {
            int s0 = __shfl_sync(0xffffffffu, (lane == 0) ? g_csr[i] : 0, 0);
            uint2 kr = *((const uint2*)(g_kh + (size_t)s0 * DDIM) + lane);
            uint2 vr = *((const uint2*)(g_vh + (size_t)s0 * DDIM) + lane);
            float2 k0 = __half22float2(*(__half2*)&kr.x);
            float2 k1 = __half22float2(*(__half2*)&kr.y);
            float p = k0.x * qf0.x + k0.y * qf0.y + k1.x * qf1.x + k1.y * qf1.y;
            p += __shfl_xor_sync(0xffffffffu, p, 1);
            p += __shfl_xor_sync(0xffffffffu, p, 2);
            float e0 = __expf(p);
            den += e0;
            float2 v0 = __half22float2(*(__half2*)&vr.x);
            float2 v1 = __half22float2(*(__half2*)&vr.y);
            acc.x += e0 * v0.x; acc.y += e0 * v0.y;
            acc.z += e0 * v1.x; acc.w += e0 * v1.y;
        }
    }

    // odd warp publishes its partial
    if (half) {
        s_part[pair][lane][0] = acc.x;
        s_part[pair][lane][1] = acc.y;
        s_part[pair][lane][2] = acc.z;
        s_part[pair][lane][3] = acc.w;
        s_part[pair][lane][4] = den;
    }
    __syncthreads();
    if (!half && valid) {
        acc.x += s_part[pair][lane][0];
        acc.y += s_part[pair][lane][1];
        acc.z += s_part[pair][lane][2];
        acc.w += s_part[pair][lane][3];
        den   += s_part[pair][lane][4];
        float inv = 1.f / (den + 1e-16f);
        __half2 o0 = __floats2half2_rn(acc.x * inv, acc.y * inv);
        __half2 o1 = __floats2half2_rn(acc.z * inv, acc.w * inv);
        uint2 o;
        o.x = *(unsigned*)&o0;
        o.y = *(unsigned*)&o1;
        *((uint2*)(g_aggt + (size_t)node * DDIM) + lane) = o;
    }
}

// ---------------- BatchNorm apply -------------------------------------------
__global__ void bn_apply_kernel(const float* __restrict__ X, int off,
                                const float* __restrict__ gamma,
                                const float* __restrict__ beta,
                                float* __restrict__ Y,
                                __half* __restrict__ Yt) {
    int i = blockIdx.x * blockDim.x + threadIdx.x;
    if (i >= NNODES * DDIM) return;
    int j = i & (DDIM - 1);
    const float invn = 1.0f / NNODES;
    float mean = g_stats[off + j] * invn;
    float var = g_stats[off + DDIM + j] * invn - mean * mean;
    float val = (X[i] - mean) * rsqrtf(var + EPS_BN) * gamma[j] + beta[j];
    Y[i] = val;
    if (Yt) Yt[i] = __float2half_rn(val);
}

// ---------------- launch ------------------------------------------------------
extern "C" void kernel_launch(void* const* d_in, const int* in_sizes, int n_in,
                              void* d_out, int out_size) {
    const float* src    = (const float*)d_in[0];
    const unsigned int* ei = (const unsigned int*)d_in[1];
    const float* q_w    = (const float*)d_in[2];
    const float* q_b    = (const float*)d_in[3];
    const float* k_w    = (const float*)d_in[4];
    const float* v_w    = (const float*)d_in[5];
    const float* out_w  = (const float*)d_in[6];
    const float* out_b  = (const float*)d_in[7];
    const float* g1     = (const float*)d_in[8];
    const float* b1     = (const float*)d_in[9];
    const float* lin1_w = (const float*)d_in[10];
    const float* lin1_b = (const float*)d_in[11];
    const float* lin2_w = (const float*)d_in[12];
    const float* lin2_b = (const float*)d_in[13];
    const float* g2     = (const float*)d_in[14];
    const float* b2     = (const float*)d_in[15];
    float* out = (float*)d_out;

    __half *paggt, *px1t, *pff1t, *pwt;
    float *px1, *ptmp;
    cudaGetSymbolAddress((void**)&paggt, g_aggt);
    cudaGetSymbolAddress((void**)&px1,   g_x1);
    cudaGetSymbolAddress((void**)&px1t,  g_x1t);
    cudaGetSymbolAddress((void**)&ptmp,  g_tmp);
    cudaGetSymbolAddress((void**)&pff1t, g_ff1t);
    cudaGetSymbolAddress((void**)&pwt,   g_wt);

    static cudaStream_t s1 = nullptr;
    static cudaEvent_t e0 = nullptr, e1 = nullptr;
    if (s1 == nullptr) {
        cudaStreamCreateWithFlags(&s1, cudaStreamNonBlocking);
        cudaEventCreateWithFlags(&e0, cudaEventDisableTiming);
        cudaEventCreateWithFlags(&e1, cudaEventDisableTiming);
    }

    const int MB = (NNODES + GM - 1) / GM;  // 391

    convert_kernel<<<512, 256>>>(src, q_w, k_w, v_w, out_w, lin1_w, lin2_w, ei);
    cudaEventRecord(e0, 0);

    cudaStreamWaitEvent(s1, e0, 0);
    decode_kernel<<<(ETOT + 255) / 256, 256, 0, s1>>>(ei);
    scan1_kernel<<<NCHUNK, 1024, 0, s1>>>();
    scan3_kernel<<<(NNODES + 255) / 256, 256, 0, s1>>>();
    scatter_kernel<<<(ETOT + 255) / 256, 256, 0, s1>>>();
    cudaEventRecord(e1, s1);

    qkv_gemm_kernel<<<dim3(1, MB, 3), 256>>>(q_b);
    cudaStreamWaitEvent(0, e1, 0);

    // attention aggregation (CSR, two warps per node)
    node_agg_kernel<<<(NNODES + 3) / 4, 256>>>();

    // out projection + residual + fused BN1 stats
    gemm_kernel<<<dim3(1, MB), 256>>>(paggt, pwt + WO_OFF, out_b, src,
                                      ptmp, nullptr, NNODES, DDIM, DDIM,
                                      1.0f, 0, 0);

    // BN1 apply (fp32 + fp16)
    bn_apply_kernel<<<(NNODES * DDIM + 255) / 256, 256>>>(ptmp, 0, g1, b1,
                                                          px1, px1t);

    // FFN
    gemm_kernel<<<dim3(FDIM / GN, MB), 256>>>(px1t, pwt + W1_OFF, lin1_b,
                                              nullptr, nullptr, pff1t,
                                              NNODES, FDIM, DDIM, 1.0f, 1, -1);
    gemm_kernel<<<dim3(1, MB), 256>>>(pff1t, pwt + W2_OFF, lin2_b, px1,
                                      ptmp, nullptr, NNODES, DDIM, FDIM,
                                      1.0f, 0, 256);

    // BN2 apply -> output
    bn_apply_kernel<<<(NNODES * DDIM + 255) / 256, 256>>>(ptmp, 256, g2, b2,
                                                          out, nullptr);
}

// round 16
// speedup vs baseline: 1.1078x; 1.1078x over previous
#include <cuda_runtime.h>
#include <cuda_fp16.h>
#include <cstdint>

#define NNODES 50000
#define DDIM 128
#define NH 8
#define HDIM 16
#define FDIM 512
#define E0 800000
#define ETOT 850000
#define EPS_BN 1e-5f
#define NCHUNK 49   // ceil(50000/1024)

// ---------------- scratch (device globals; no allocation allowed) ----------
__device__ __align__(16) __half g_qh[NNODES * DDIM];
__device__ __align__(16) __half g_kh[NNODES * DDIM];
__device__ __align__(16) __half g_vh[NNODES * DDIM];
__device__ __align__(16) __half g_aggt[NNODES * DDIM];
__device__ __align__(16) float  g_x1[NNODES * DDIM];
__device__ __align__(16) __half g_x1t[NNODES * DDIM];
__device__ __align__(16) float  g_tmp[NNODES * DDIM];
__device__ __align__(16) __half g_ff1t[(size_t)NNODES * FDIM];
__device__ __align__(16) __half g_srct[NNODES * DDIM];
__device__ __align__(16) __half g_wt[196608];
__device__ __align__(16) float  g_stats[512];
__device__ int g_src[ETOT];
__device__ int g_dst[ETOT];
__device__ int g_csr[ETOT];
__device__ int g_deg[NNODES];
__device__ int g_rowptr[NNODES + 1];
__device__ int g_cursor[NNODES];
__device__ int g_csum[64];
__device__ int g_is64;

#define WQ_OFF 0
#define WK_OFF 16384
#define WV_OFF 32768
#define WO_OFF 49152
#define W1_OFF 65536
#define W2_OFF 131072
#define NSRC (NNODES * DDIM)
#define NSRC4 (NSRC / 4)
#define NW4 (196608 / 4)
#define NCONV4 (NSRC4 + NW4)

// ---------------- convert + prep: vectorized fp16 convert, detect, zero -----
__global__ void convert_kernel(const float* __restrict__ src,
                               const float* __restrict__ wq,
                               const float* __restrict__ wk,
                               const float* __restrict__ wv,
                               const float* __restrict__ wo,
                               const float* __restrict__ w1,
                               const float* __restrict__ w2,
                               const unsigned int* __restrict__ ew) {
    int i = blockIdx.x * blockDim.x + threadIdx.x;
    if (i == 0) {
        int nz = 0;
        for (int j = 1; j < 256; j += 2) nz += (ew[j] != 0u);
        g_is64 = (nz == 0) ? 1 : 0;
    }
    if (i < NNODES) g_deg[i] = 0;
    if (i < 512) g_stats[i] = 0.f;
    int stride = gridDim.x * blockDim.x;
    for (int t = i; t < NCONV4; t += stride) {
        float4 v;
        uint2* dst;
        if (t < NSRC4) {
            v = ((const float4*)src)[t];
            dst = (uint2*)g_srct + t;
        } else {
            int j = (t - NSRC4) * 4;   // element offset in g_wt
            const float* p;
            if (j < WK_OFF)      p = wq + (j - WQ_OFF);
            else if (j < WV_OFF) p = wk + (j - WK_OFF);
            else if (j < WO_OFF) p = wv + (j - WV_OFF);
            else if (j < W1_OFF) p = wo + (j - WO_OFF);
            else if (j < W2_OFF) p = w1 + (j - W1_OFF);
            else                 p = w2 + (j - W2_OFF);
            v = *(const float4*)p;
            dst = (uint2*)(g_wt + j);
        }
        __half2 h0 = __floats2half2_rn(v.x, v.y);
        __half2 h1 = __floats2half2_rn(v.z, v.w);
        uint2 o;
        o.x = *(unsigned*)&h0;
        o.y = *(unsigned*)&h1;
        *dst = o;
    }
}

// ---------------- decode edges + degree histogram ---------------------------
__global__ void decode_kernel(const unsigned int* __restrict__ w) {
    int e = blockIdx.x * blockDim.x + threadIdx.x;
    if (e >= ETOT) return;
    int s, d;
    if (e < E0) {
        if (g_is64) {
            s = (int)w[2 * (size_t)e];
            d = (int)w[2 * ((size_t)E0 + e)];
        } else {
            s = (int)w[e];
            d = (int)w[E0 + e];
        }
    } else {
        s = d = e - E0;
    }
    g_src[e] = s;
    g_dst[e] = d;
    atomicAdd(&g_deg[d], 1);
}

// ---------------- CSR build --------------------------------------------------
__global__ void scan1_kernel() {
    __shared__ int sh[1024];
    int t = threadIdx.x;
    int i = blockIdx.x * 1024 + t;
    int v = (i < NNODES) ? g_deg[i] : 0;
    sh[t] = v;
    __syncthreads();
    for (int off = 1; off < 1024; off <<= 1) {
        int x = (t >= off) ? sh[t - off] : 0;
        __syncthreads();
        sh[t] += x;
        __syncthreads();
    }
    if (i < NNODES) g_rowptr[i] = sh[t] - v;
    if (t == 1023) g_csum[blockIdx.x] = sh[1023];
}

__global__ void scan3_kernel() {
    __shared__ int pref;
    if (threadIdx.x == 0) {
        int c = (blockIdx.x * 256) >> 10;
        int run = 0;
        for (int j = 0; j < c; j++) run += g_csum[j];
        pref = run;
    }
    __syncthreads();
    int i = blockIdx.x * blockDim.x + threadIdx.x;
    if (i < NNODES) {
        int rp = g_rowptr[i] + pref;
        g_rowptr[i] = rp;
        g_cursor[i] = rp;
    }
    if (i == 0) g_rowptr[NNODES] = ETOT;
}

__global__ void scatter_kernel() {
    int e = blockIdx.x * blockDim.x + threadIdx.x;
    if (e >= ETOT) return;
    int pos = atomicAdd(&g_cursor[g_dst[e]], 1);
    g_csr[pos] = g_src[e];
}

// ---------------- FP16 tensor-core GEMM (m16n8k16 + ldmatrix) ---------------
#define GM 128
#define GN 128
#define KT 32
#define SK 20
#define BUFB (GM * SK * 4)

__device__ __forceinline__ void mma16(float c[4],
                                      unsigned a0, unsigned a1, unsigned a2, unsigned a3,
                                      unsigned b0, unsigned b1) {
    asm volatile(
        "mma.sync.aligned.m16n8k16.row.col.f32.f16.f16.f32 "
        "{%0,%1,%2,%3}, {%4,%5,%6,%7}, {%8,%9}, {%0,%1,%2,%3};"
        : "+f"(c[0]), "+f"(c[1]), "+f"(c[2]), "+f"(c[3])
        : "r"(a0), "r"(a1), "r"(a2), "r"(a3), "r"(b0), "r"(b1));
}

#define LDSM4(r0, r1, r2, r3, addr) \
    asm volatile("ldmatrix.sync.aligned.m8n8.x4.shared.b16 {%0,%1,%2,%3}, [%4];" \
                 : "=r"(r0), "=r"(r1), "=r"(r2), "=r"(r3) : "r"(addr))

__device__ __forceinline__ float2 lrelu2(float2 o, int act) {
    if (act) {
        o.x = o.x > 0.f ? o.x : 0.01f * o.x;
        o.y = o.y > 0.f ? o.y : 0.01f * o.y;
    }
    return o;
}

__device__ __forceinline__ void gemm_body(
    const __half* __restrict__ A, const __half* __restrict__ B,
    const float* __restrict__ bias, const float* __restrict__ res,
    float* __restrict__ C, __half* __restrict__ Ct,
    int M, int Nn, int K, float alpha, int act, int stats_off,
    int bm, int bn)
{
    __shared__ __align__(16) unsigned As[2][GM][SK];
    __shared__ __align__(16) unsigned Bs[2][GN][SK];
    int tid = threadIdx.x;
    int warp = tid >> 5, lane = tid & 31;
    int wm = warp >> 2, wn = warp & 3;
    int gid = lane >> 2, ctg = lane & 3;
    int lg = lane >> 3, l8 = lane & 7;

    int lrow = tid & 127;
    int kh = (tid >> 7) * 8;
    int kw = K >> 1;
    const unsigned* Ap = (const unsigned*)A + (size_t)(bm + lrow) * kw + kh;
    const unsigned* Bp = (const unsigned*)B + (size_t)(bn + lrow) * kw + kh;
    bool aok = (bm + lrow) < M;

    unsigned sA = (unsigned)__cvta_generic_to_shared(&As[0][0][0]);
    unsigned sB = (unsigned)__cvta_generic_to_shared(&Bs[0][0][0]);
    unsigned aBase = sA + (unsigned)((wm * 64 + (lg & 1) * 8 + l8) * (SK * 4)
                                     + (lg >> 1) * 16);
    unsigned bBase = sB + (unsigned)((wn * 32 + (lg >> 1) * 8 + l8) * (SK * 4)
                                     + (lg & 1) * 16);

    float c[4][4][4];
#pragma unroll
    for (int mt = 0; mt < 4; mt++)
#pragma unroll
        for (int nt = 0; nt < 4; nt++)
#pragma unroll
            for (int r = 0; r < 4; r++) c[mt][nt][r] = 0.f;

    const uint4 z4 = make_uint4(0u, 0u, 0u, 0u);
    uint4 a0v = aok ? *(const uint4*)Ap : z4;
    uint4 a1v = aok ? *(const uint4*)(Ap + 4) : z4;
    uint4 b0v = *(const uint4*)Bp;
    uint4 b1v = *(const uint4*)(Bp + 4);
    *(uint4*)&As[0][lrow][kh]     = a0v;
    *(uint4*)&As[0][lrow][kh + 4] = a1v;
    *(uint4*)&Bs[0][lrow][kh]     = b0v;
    *(uint4*)&Bs[0][lrow][kh + 4] = b1v;
    __syncthreads();

    int nk = K / KT;
    for (int kt = 0; kt < nk; kt++) {
        int cur = kt & 1;
        int nxt = cur ^ 1;
        bool more = (kt + 1) < nk;
        if (more) {
            int off = (kt + 1) * 16;
            a0v = aok ? *(const uint4*)(Ap + off) : z4;
            a1v = aok ? *(const uint4*)(Ap + off + 4) : z4;
            b0v = *(const uint4*)(Bp + off);
            b1v = *(const uint4*)(Bp + off + 4);
        }
        unsigned aB = aBase + cur * BUFB;
        unsigned bB = bBase + cur * BUFB;
#pragma unroll
        for (int ks = 0; ks < 2; ks++) {
            unsigned ksoff = ks * 32;
            unsigned af[4][4], bf[4][2];
#pragma unroll
            for (int mt = 0; mt < 4; mt++)
                LDSM4(af[mt][0], af[mt][1], af[mt][2], af[mt][3],
                      aB + mt * (16 * SK * 4) + ksoff);
#pragma unroll
            for (int np = 0; np < 2; np++)
                LDSM4(bf[np * 2][0], bf[np * 2][1], bf[np * 2 + 1][0],
                      bf[np * 2 + 1][1], bB + np * (16 * SK * 4) + ksoff);
#pragma unroll
            for (int mt = 0; mt < 4; mt++)
#pragma unroll
                for (int nt = 0; nt < 4; nt++)
                    mma16(c[mt][nt], af[mt][0], af[mt][1], af[mt][2], af[mt][3],
                          bf[nt][0], bf[nt][1]);
        }
        if (more) {
            *(uint4*)&As[nxt][lrow][kh]     = a0v;
            *(uint4*)&As[nxt][lrow][kh + 4] = a1v;
            *(uint4*)&Bs[nxt][lrow][kh]     = b0v;
            *(uint4*)&Bs[nxt][lrow][kh + 4] = b1v;
            __syncthreads();
        }
    }

    float ssum[4][2] = {}, ssq[4][2] = {};
#pragma unroll
    for (int nt = 0; nt < 4; nt++) {
        int col = bn + wn * 32 + nt * 8 + 2 * ctg;
        float2 bb = make_float2(0.f, 0.f);
        if (bias) bb = *(const float2*)(bias + col);
#pragma unroll
        for (int mt = 0; mt < 4; mt++) {
            int r0 = bm + wm * 64 + mt * 16 + gid;
            int r1 = r0 + 8;
            if (r0 < M) {
                float2 rv = res ? *(const float2*)(res + (size_t)r0 * Nn + col)
                                : make_float2(0.f, 0.f);
                float2 o;
                o.x = (c[mt][nt][0] + bb.x) * alpha + rv.x;
                o.y = (c[mt][nt][1] + bb.y) * alpha + rv.y;
                o = lrelu2(o, act);
                if (C) *(float2*)(C + (size_t)r0 * Nn + col) = o;
                if (Ct) *(__half2*)(Ct + (size_t)r0 * Nn + col) =
                            __floats2half2_rn(o.x, o.y);
                ssum[nt][0] += o.x; ssum[nt][1] += o.y;
                ssq[nt][0] += o.x * o.x; ssq[nt][1] += o.y * o.y;
            }
            if (r1 < M) {
                float2 rv = res ? *(const float2*)(res + (size_t)r1 * Nn + col)
                                : make_float2(0.f, 0.f);
                float2 o;
                o.x = (c[mt][nt][2] + bb.x) * alpha + rv.x;
                o.y = (c[mt][nt][3] + bb.y) * alpha + rv.y;
                o = lrelu2(o, act);
                if (C) *(float2*)(C + (size_t)r1 * Nn + col) = o;
                if (Ct) *(__half2*)(Ct + (size_t)r1 * Nn + col) =
                            __floats2half2_rn(o.x, o.y);
                ssum[nt][0] += o.x; ssum[nt][1] += o.y;
                ssq[nt][0] += o.x * o.x; ssq[nt][1] += o.y * o.y;
            }
        }
    }

    if (stats_off >= 0) {
        __syncthreads();
        float* sh = (float*)&As[0][0][0];
        sh[tid] = 0.f;
        __syncthreads();
#pragma unroll
        for (int nt = 0; nt < 4; nt++) {
            int cl = wn * 32 + nt * 8 + 2 * ctg;
            atomicAdd(&sh[cl], ssum[nt][0]);
            atomicAdd(&sh[cl + 1], ssum[nt][1]);
            atomicAdd(&sh[128 + cl], ssq[nt][0]);
            atomicAdd(&sh[128 + cl + 1], ssq[nt][1]);
        }
        __syncthreads();
        atomicAdd(&g_stats[stats_off + tid], sh[tid]);
    }
}

__global__ __launch_bounds__(256, 2) void gemm_kernel(
    const __half* __restrict__ A, const __half* __restrict__ B,
    const float* __restrict__ bias, const float* __restrict__ res,
    float* __restrict__ C, __half* __restrict__ Ct,
    int M, int Nn, int K, float alpha, int act, int stats_off)
{
    gemm_body(A, B, bias, res, C, Ct, M, Nn, K, alpha, act, stats_off,
              blockIdx.y * GM, blockIdx.x * GN);
}

__global__ __launch_bounds__(256, 2) void qkv_gemm_kernel(const float* __restrict__ qb) {
    int z = blockIdx.z;
    const __half* B = g_wt + ((z == 0) ? WQ_OFF : (z == 1) ? WK_OFF : WV_OFF);
    __half* Ct = (z == 0) ? g_qh : (z == 1) ? g_kh : g_vh;
    const float* bias = (z == 0) ? qb : nullptr;
    float alpha = (z == 0) ? 0.25f : 1.0f;
    gemm_body(g_srct, B, bias, nullptr, nullptr, Ct,
              NNODES, DDIM, DDIM, alpha, 0, -1, blockIdx.y * GM, 0);
}

// ---------------- warp-per-node CSR attention aggregation (R14 version) -----
__global__ void node_agg_kernel() {
    int node = (blockIdx.x * blockDim.x + threadIdx.x) >> 5;
    if (node >= NNODES) return;
    int lane = threadIdx.x & 31;
    uint2 qa = *((const uint2*)(g_qh + (size_t)node * DDIM) + lane);
    float2 qf0 = __half22float2(*(__half2*)&qa.x);
    float2 qf1 = __half22float2(*(__half2*)&qa.y);
    float4 acc = make_float4(0.f, 0.f, 0.f, 0.f);
    float den = 0.f;
    int beg = g_rowptr[node], end = g_rowptr[node + 1];
    int i = beg;
    int esel = lane & 3;
    int gbase = lane & ~3;
    for (; i + 4 <= end; i += 4) {
        int sv = (lane < 4) ? g_csr[i + lane] : 0;
        int s[4];
#pragma unroll
        for (int j = 0; j < 4; j++) s[j] = __shfl_sync(0xffffffffu, sv, j);
        uint2 kr[4], vr[4];
#pragma unroll
        for (int j = 0; j < 4; j++)
            kr[j] = *((const uint2*)(g_kh + (size_t)s[j] * DDIM) + lane);
#pragma unroll
        for (int j = 0; j < 4; j++)
            vr[j] = *((const uint2*)(g_vh + (size_t)s[j] * DDIM) + lane);
        float p[4];
#pragma unroll
        for (int j = 0; j < 4; j++) {
            float2 k0 = __half22float2(*(__half2*)&kr[j].x);
            float2 k1 = __half22float2(*(__half2*)&kr[j].y);
            p[j] = k0.x * qf0.x + k0.y * qf0.y + k1.x * qf1.x + k1.y * qf1.y;
            p[j] += __shfl_xor_sync(0xffffffffu, p[j], 1);
            p[j] += __shfl_xor_sync(0xffffffffu, p[j], 2);
        }
        float eo = __expf(esel == 0 ? p[0] : esel == 1 ? p[1]
                          : esel == 2 ? p[2] : p[3]);
        float e[4];
#pragma unroll
        for (int j = 0; j < 4; j++)
            e[j] = __shfl_sync(0xffffffffu, eo, gbase + j);
#pragma unroll
        for (int j = 0; j < 4; j++) {
            den += e[j];
            float2 v0 = __half22float2(*(__half2*)&vr[j].x);
            float2 v1 = __half22float2(*(__half2*)&vr[j].y);
            acc.x += e[j] * v0.x; acc.y += e[j] * v0.y;
            acc.z += e[j] * v1.x; acc.w += e[j] * v1.y;
        }
    }
    for (; i < end; i++) {
        int s0 = __shfl_sync(0xffffffffu, (lane == 0) ? g_csr[i] : 0, 0);
        uint2 kr = *((const uint2*)(g_kh + (size_t)s0 * DDIM) + lane);
        uint2 vr = *((const uint2*)(g_vh + (size_t)s0 * DDIM) + lane);
        float2 k0 = __half22float2(*(__half2*)&kr.x);
        float2 k1 = __half22float2(*(__half2*)&kr.y);
        float p = k0.x * qf0.x + k0.y * qf0.y + k1.x * qf1.x + k1.y * qf1.y;
        p += __shfl_xor_sync(0xffffffffu, p, 1);
        p += __shfl_xor_sync(0xffffffffu, p, 2);
        float e0 = __expf(p);
        den += e0;
        float2 v0 = __half22float2(*(__half2*)&vr.x);
        float2 v1 = __half22float2(*(__half2*)&vr.y);
        acc.x += e0 * v0.x; acc.y += e0 * v0.y;
        acc.z += e0 * v1.x; acc.w += e0 * v1.y;
    }
    float inv = 1.f / (den + 1e-16f);
    __half2 o0 = __floats2half2_rn(acc.x * inv, acc.y * inv);
    __half2 o1 = __floats2half2_rn(acc.z * inv, acc.w * inv);
    uint2 o;
    o.x = *(unsigned*)&o0;
    o.y = *(unsigned*)&o1;
    *((uint2*)(g_aggt + (size_t)node * DDIM) + lane) = o;
}

// ---------------- BatchNorm apply (vectorized: 4 elems/thread) --------------
__global__ void bn_apply_kernel(const float* __restrict__ X, int off,
                                const float* __restrict__ gamma,
                                const float* __restrict__ beta,
                                float* __restrict__ Y,
                                __half* __restrict__ Yt) {
    int t = blockIdx.x * blockDim.x + threadIdx.x;
    if (t >= NSRC4) return;
    int i = t * 4;
    int j = i & (DDIM - 1);
    const float invn = 1.0f / NNODES;
    float4 x = *(const float4*)(X + i);
    float4 gm = *(const float4*)(gamma + j);
    float4 bt = *(const float4*)(beta + j);
    float4 sm = *(const float4*)(g_stats + off + j);
    float4 sq = *(const float4*)(g_stats + off + DDIM + j);
    float4 o;
    {
        float mean = sm.x * invn, var = sq.x * invn - mean * mean;
        o.x = (x.x - mean) * rsqrtf(var + EPS_BN) * gm.x + bt.x;
    }
    {
        float mean = sm.y * invn, var = sq.y * invn - mean * mean;
        o.y = (x.y - mean) * rsqrtf(var + EPS_BN) * gm.y + bt.y;
    }
    {
        float mean = sm.z * invn, var = sq.z * invn - mean * mean;
        o.z = (x.z - mean) * rsqrtf(var + EPS_BN) * gm.z + bt.z;
    }
    {
        float mean = sm.w * invn, var = sq.w * invn - mean * mean;
        o.w = (x.w - mean) * rsqrtf(var + EPS_BN) * gm.w + bt.w;
    }
    *(float4*)(Y + i) = o;
    if (Yt) {
        __half2 h0 = __floats2half2_rn(o.x, o.y);
        __half2 h1 = __floats2half2_rn(o.z, o.w);
        uint2 u;
        u.x = *(unsigned*)&h0;
        u.y = *(unsigned*)&h1;
        *(uint2*)(Yt + i) = u;
    }
}

// ---------------- launch ------------------------------------------------------
extern "C" void kernel_launch(void* const* d_in, const int* in_sizes, int n_in,
                              void* d_out, int out_size) {
    const float* src    = (const float*)d_in[0];
    const unsigned int* ei = (const unsigned int*)d_in[1];
    const float* q_w    = (const float*)d_in[2];
    const float* q_b    = (const float*)d_in[3];
    const float* k_w    = (const float*)d_in[4];
    const float* v_w    = (const float*)d_in[5];
    const float* out_w  = (const float*)d_in[6];
    const float* out_b  = (const float*)d_in[7];
    const float* g1     = (const float*)d_in[8];
    const float* b1     = (const float*)d_in[9];
    const float* lin1_w = (const float*)d_in[10];
    const float* lin1_b = (const float*)d_in[11];
    const float* lin2_w = (const float*)d_in[12];
    const float* lin2_b = (const float*)d_in[13];
    const float* g2     = (const float*)d_in[14];
    const float* b2     = (const float*)d_in[15];
    float* out = (float*)d_out;

    __half *paggt, *px1t, *pff1t, *pwt;
    float *px1, *ptmp;
    cudaGetSymbolAddress((void**)&paggt, g_aggt);
    cudaGetSymbolAddress((void**)&px1,   g_x1);
    cudaGetSymbolAddress((void**)&px1t,  g_x1t);
    cudaGetSymbolAddress((void**)&ptmp,  g_tmp);
    cudaGetSymbolAddress((void**)&pff1t, g_ff1t);
    cudaGetSymbolAddress((void**)&pwt,   g_wt);

    static cudaStream_t s1 = nullptr;
    static cudaEvent_t e0 = nullptr, e1 = nullptr;
    if (s1 == nullptr) {
        cudaStreamCreateWithFlags(&s1, cudaStreamNonBlocking);
        cudaEventCreateWithFlags(&e0, cudaEventDisableTiming);
        cudaEventCreateWithFlags(&e1, cudaEventDisableTiming);
    }

    const int MB = (NNODES + GM - 1) / GM;  // 391

    convert_kernel<<<512, 256>>>(src, q_w, k_w, v_w, out_w, lin1_w, lin2_w, ei);
    cudaEventRecord(e0, 0);

    cudaStreamWaitEvent(s1, e0, 0);
    decode_kernel<<<(ETOT + 255) / 256, 256, 0, s1>>>(ei);
    scan1_kernel<<<NCHUNK, 1024, 0, s1>>>();
    scan3_kernel<<<(NNODES + 255) / 256, 256, 0, s1>>>();
    scatter_kernel<<<(ETOT + 255) / 256, 256, 0, s1>>>();
    cudaEventRecord(e1, s1);

    qkv_gemm_kernel<<<dim3(1, MB, 3), 256>>>(q_b);
    cudaStreamWaitEvent(0, e1, 0);

    // attention aggregation (CSR, warp per node)
    node_agg_kernel<<<(NNODES * 32 + 255) / 256, 256>>>();

    // out projection + residual + fused BN1 stats
    gemm_kernel<<<dim3(1, MB), 256>>>(paggt, pwt + WO_OFF, out_b, src,
                                      ptmp, nullptr, NNODES, DDIM, DDIM,
                                      1.0f, 0, 0);

    // BN1 apply (fp32 + fp16)
    bn_apply_kernel<<<(NSRC4 + 255) / 256, 256>>>(ptmp, 0, g1, b1, px1, px1t);

    // FFN
    gemm_kernel<<<dim3(FDIM / GN, MB), 256>>>(px1t, pwt + W1_OFF, lin1_b,
                                              nullptr, nullptr, pff1t,
                                              NNODES, FDIM, DDIM, 1.0f, 1, -1);
    gemm_kernel<<<dim3(1, MB), 256>>>(pff1t, pwt + W2_OFF, lin2_b, px1,
                                      ptmp, nullptr, NNODES, DDIM, FDIM,
                                      1.0f, 0, 256);

    // BN2 apply -> output
    bn_apply_kernel<<<(NSRC4 + 255) / 256, 256>>>(ptmp, 256, g2, b2,
                                                  out, nullptr);
}

// round 17
// speedup vs baseline: 1.1614x; 1.0483x over previous
#include <cuda_runtime.h>
#include <cuda_fp16.h>
#include <cstdint>

#define NNODES 50000
#define DDIM 128
#define NH 8
#define HDIM 16
#define FDIM 512
#define E0 800000
#define ETOT 850000
#define EPS_BN 1e-5f
#define NCHUNK 49   // ceil(50000/1024)

// ---------------- scratch (device globals; no allocation allowed) ----------
__device__ __align__(16) __half g_qh[NNODES * DDIM];
__device__ __align__(16) __half g_kh[NNODES * DDIM];
__device__ __align__(16) __half g_vh[NNODES * DDIM];
__device__ __align__(16) __half g_aggt[NNODES * DDIM];
__device__ __align__(16) float  g_x1[NNODES * DDIM];
__device__ __align__(16) __half g_x1t[NNODES * DDIM];
__device__ __align__(16) float  g_tmp[NNODES * DDIM];
__device__ __align__(16) __half g_ff1t[(size_t)NNODES * FDIM];
__device__ __align__(16) __half g_srct[NNODES * DDIM];
__device__ __align__(16) __half g_wt[196608];
__device__ __align__(16) float  g_stats[512];
__device__ int g_src[ETOT];
__device__ int g_dst[ETOT];
__device__ int g_csr[ETOT];
__device__ int g_deg[NNODES];
__device__ int g_rowptr[NNODES + 1];
__device__ int g_cursor[NNODES];
__device__ int g_csum[64];
__device__ int g_is64;

#define WQ_OFF 0
#define WK_OFF 16384
#define WV_OFF 32768
#define WO_OFF 49152
#define W1_OFF 65536
#define W2_OFF 131072
#define NSRC (NNODES * DDIM)
#define NSRC4 (NSRC / 4)
#define NW4 (196608 / 4)
#define NCONV4 (NSRC4 + NW4)

// ---------------- convert + prep: vectorized fp16 convert, detect, zero -----
__global__ void convert_kernel(const float* __restrict__ src,
                               const float* __restrict__ wq,
                               const float* __restrict__ wk,
                               const float* __restrict__ wv,
                               const float* __restrict__ wo,
                               const float* __restrict__ w1,
                               const float* __restrict__ w2,
                               const unsigned int* __restrict__ ew) {
    int i = blockIdx.x * blockDim.x + threadIdx.x;
    if (i == 0) {
        int nz = 0;
        for (int j = 1; j < 256; j += 2) nz += (ew[j] != 0u);
        g_is64 = (nz == 0) ? 1 : 0;
    }
    if (i < NNODES) g_deg[i] = 0;
    if (i < 512) g_stats[i] = 0.f;
    int stride = gridDim.x * blockDim.x;
    for (int t = i; t < NCONV4; t += stride) {
        float4 v;
        uint2* dst;
        if (t < NSRC4) {
            v = ((const float4*)src)[t];
            dst = (uint2*)g_srct + t;
        } else {
            int j = (t - NSRC4) * 4;
            const float* p;
            if (j < WK_OFF)      p = wq + (j - WQ_OFF);
            else if (j < WV_OFF) p = wk + (j - WK_OFF);
            else if (j < WO_OFF) p = wv + (j - WV_OFF);
            else if (j < W1_OFF) p = wo + (j - WO_OFF);
            else if (j < W2_OFF) p = w1 + (j - W1_OFF);
            else                 p = w2 + (j - W2_OFF);
            v = *(const float4*)p;
            dst = (uint2*)(g_wt + j);
        }
        __half2 h0 = __floats2half2_rn(v.x, v.y);
        __half2 h1 = __floats2half2_rn(v.z, v.w);
        uint2 o;
        o.x = *(unsigned*)&h0;
        o.y = *(unsigned*)&h1;
        *dst = o;
    }
}

// ---------------- decode edges + degree histogram ---------------------------
__global__ void decode_kernel(const unsigned int* __restrict__ w) {
    int e = blockIdx.x * blockDim.x + threadIdx.x;
    if (e >= ETOT) return;
    int s, d;
    if (e < E0) {
        if (g_is64) {
            s = (int)w[2 * (size_t)e];
            d = (int)w[2 * ((size_t)E0 + e)];
        } else {
            s = (int)w[e];
            d = (int)w[E0 + e];
        }
    } else {
        s = d = e - E0;
    }
    g_src[e] = s;
    g_dst[e] = d;
    atomicAdd(&g_deg[d], 1);
}

// ---------------- CSR build --------------------------------------------------
__global__ void scan1_kernel() {
    __shared__ int sh[1024];
    int t = threadIdx.x;
    int i = blockIdx.x * 1024 + t;
    int v = (i < NNODES) ? g_deg[i] : 0;
    sh[t] = v;
    __syncthreads();
    for (int off = 1; off < 1024; off <<= 1) {
        int x = (t >= off) ? sh[t - off] : 0;
        __syncthreads();
        sh[t] += x;
        __syncthreads();
    }
    if (i < NNODES) g_rowptr[i] = sh[t] - v;
    if (t == 1023) g_csum[blockIdx.x] = sh[1023];
}

__global__ void scan3_kernel() {
    __shared__ int pref;
    if (threadIdx.x == 0) {
        int c = (blockIdx.x * 256) >> 10;
        int run = 0;
        for (int j = 0; j < c; j++) run += g_csum[j];
        pref = run;
    }
    __syncthreads();
    int i = blockIdx.x * blockDim.x + threadIdx.x;
    if (i < NNODES) {
        int rp = g_rowptr[i] + pref;
        g_rowptr[i] = rp;
        g_cursor[i] = rp;
    }
    if (i == 0) g_rowptr[NNODES] = ETOT;
}

__global__ void scatter_kernel() {
    int e = blockIdx.x * blockDim.x + threadIdx.x;
    if (e >= ETOT) return;
    int pos = atomicAdd(&g_cursor[g_dst[e]], 1);
    g_csr[pos] = g_src[e];
}

// ---------------- FP16 tensor-core GEMM: cp.async 4-stage + ldmatrix --------
#define GM 128
#define GN 128
#define KT 32
#define SK 20
#define STAGES 4
#define TILEW (GM * SK)        // words per array per stage
#define TILEB (TILEW * 4)      // 10240 bytes
#define BOFFB (STAGES * TILEB) // B region offset
#define SMEMB (2 * STAGES * TILEB)  // 81920 bytes

__device__ __forceinline__ void mma16(float c[4],
                                      unsigned a0, unsigned a1, unsigned a2, unsigned a3,
                                      unsigned b0, unsigned b1) {
    asm volatile(
        "mma.sync.aligned.m16n8k16.row.col.f32.f16.f16.f32 "
        "{%0,%1,%2,%3}, {%4,%5,%6,%7}, {%8,%9}, {%0,%1,%2,%3};"
        : "+f"(c[0]), "+f"(c[1]), "+f"(c[2]), "+f"(c[3])
        : "r"(a0), "r"(a1), "r"(a2), "r"(a3), "r"(b0), "r"(b1));
}

#define LDSM4(r0, r1, r2, r3, addr) \
    asm volatile("ldmatrix.sync.aligned.m8n8.x4.shared.b16 {%0,%1,%2,%3}, [%4];" \
                 : "=r"(r0), "=r"(r1), "=r"(r2), "=r"(r3) : "r"(addr))

#define CP16(dst, src, sz) \
    asm volatile("cp.async.ca.shared.global [%0], [%1], 16, %2;" \
                 :: "r"(dst), "l"(src), "r"(sz))
#define CPCOMMIT() asm volatile("cp.async.commit_group;")
#define CPWAIT(n) asm volatile("cp.async.wait_group %0;" :: "n"(n))

__device__ __forceinline__ float2 lrelu2(float2 o, int act) {
    if (act) {
        o.x = o.x > 0.f ? o.x : 0.01f * o.x;
        o.y = o.y > 0.f ? o.y : 0.01f * o.y;
    }
    return o;
}

__device__ __forceinline__ void gemm_body(
    const __half* __restrict__ A, const __half* __restrict__ B,
    const float* __restrict__ bias, const float* __restrict__ res,
    float* __restrict__ C, __half* __restrict__ Ct,
    int M, int Nn, int K, float alpha, int act, int stats_off,
    int bm, int bn)
{
    extern __shared__ __align__(16) unsigned dynsm[];
    int tid = threadIdx.x;
    int warp = tid >> 5, lane = tid & 31;
    int wm = warp >> 2, wn = warp & 3;
    int gid = lane >> 2, ctg = lane & 3;
    int lg = lane >> 3, l8 = lane & 7;

    int lrow = tid & 127;
    int kh = (tid >> 7) * 8;
    int kw = K >> 1;
    int arow = bm + lrow;
    bool aok = arow < M;
    if (!aok) arow = M - 1;  // clamp: src-size 0 -> zero-fill, no OOB read
    const unsigned* Ap = (const unsigned*)A + (size_t)arow * kw + kh;
    const unsigned* Bp = (const unsigned*)B + (size_t)(bn + lrow) * kw + kh;
    unsigned asz = aok ? 16u : 0u;

    unsigned sb = (unsigned)__cvta_generic_to_shared(dynsm);
    unsigned ldst = sb + (unsigned)((lrow * SK + kh) * 4);  // stage 0 A dst
    unsigned aBase = sb + (unsigned)(((wm * 64 + (lg & 1) * 8 + l8) * SK) * 4
                                     + (lg >> 1) * 16);
    unsigned bBase = sb + BOFFB + (unsigned)(((wn * 32 + (lg >> 1) * 8 + l8) * SK) * 4
                                             + (lg & 1) * 16);

    float c[4][4][4];
#pragma unroll
    for (int mt = 0; mt < 4; mt++)
#pragma unroll
        for (int nt = 0; nt < 4; nt++)
#pragma unroll
            for (int r = 0; r < 4; r++) c[mt][nt][r] = 0.f;

    int nk = K / KT;
    // prologue: issue tiles 0..STAGES-2 (nk >= 4 always here)
#pragma unroll
    for (int t = 0; t < STAGES - 1; t++) {
        unsigned ad = ldst + t * TILEB;
        const unsigned* as = Ap + t * 16;
        const unsigned* bs = Bp + t * 16;
        CP16(ad, as, asz);
        CP16(ad + 16, as + 4, asz);
        CP16(ad + BOFFB, bs, 16u);
        CP16(ad + BOFFB + 16, bs + 4, 16u);
        CPCOMMIT();
    }

    for (int kt = 0; kt < nk; kt++) {
        CPWAIT(STAGES - 2);
        __syncthreads();
        // issue tile kt+3 into stage (kt+3)%4 (== stage of tile kt-1, fully consumed)
        int nx = kt + STAGES - 1;
        if (nx < nk) {
            unsigned ad = ldst + (nx % STAGES) * TILEB;
            const unsigned* as = Ap + nx * 16;
            const unsigned* bs = Bp + nx * 16;
            CP16(ad, as, asz);
            CP16(ad + 16, as + 4, asz);
            CP16(ad + BOFFB, bs, 16u);
            CP16(ad + BOFFB + 16, bs + 4, 16u);
        }
        CPCOMMIT();

        unsigned stoff = (kt % STAGES) * TILEB;
        unsigned aB = aBase + stoff;
        unsigned bB = bBase + stoff;
#pragma unroll
        for (int ks = 0; ks < 2; ks++) {
            unsigned ksoff = ks * 32;
            unsigned af[4][4], bf[4][2];
#pragma unroll
            for (int mt = 0; mt < 4; mt++)
                LDSM4(af[mt][0], af[mt][1], af[mt][2], af[mt][3],
                      aB + mt * (16 * SK * 4) + ksoff);
#pragma unroll
            for (int np = 0; np < 2; np++)
                LDSM4(bf[np * 2][0], bf[np * 2][1], bf[np * 2 + 1][0],
                      bf[np * 2 + 1][1], bB + np * (16 * SK * 4) + ksoff);
#pragma unroll
            for (int mt = 0; mt < 4; mt++)
#pragma unroll
                for (int nt = 0; nt < 4; nt++)
                    mma16(c[mt][nt], af[mt][0], af[mt][1], af[mt][2], af[mt][3],
                          bf[nt][0], bf[nt][1]);
        }
    }
    CPWAIT(0);

    float ssum[4][2] = {}, ssq[4][2] = {};
#pragma unroll
    for (int nt = 0; nt < 4; nt++) {
        int col = bn + wn * 32 + nt * 8 + 2 * ctg;
        float2 bb = make_float2(0.f, 0.f);
        if (bias) bb = *(const float2*)(bias + col);
#pragma unroll
        for (int mt = 0; mt < 4; mt++) {
            int r0 = bm + wm * 64 + mt * 16 + gid;
            int r1 = r0 + 8;
            if (r0 < M) {
                float2 rv = res ? *(const float2*)(res + (size_t)r0 * Nn + col)
                                : make_float2(0.f, 0.f);
                float2 o;
                o.x = (c[mt][nt][0] + bb.x) * alpha + rv.x;
                o.y = (c[mt][nt][1] + bb.y) * alpha + rv.y;
                o = lrelu2(o, act);
                if (C) *(float2*)(C + (size_t)r0 * Nn + col) = o;
                if (Ct) *(__half2*)(Ct + (size_t)r0 * Nn + col) =
                            __floats2half2_rn(o.x, o.y);
                ssum[nt][0] += o.x; ssum[nt][1] += o.y;
                ssq[nt][0] += o.x * o.x; ssq[nt][1] += o.y * o.y;
            }
            if (r1 < M) {
                float2 rv = res ? *(const float2*)(res + (size_t)r1 * Nn + col)
                                : make_float2(0.f, 0.f);
                float2 o;
                o.x = (c[mt][nt][2] + bb.x) * alpha + rv.x;
                o.y = (c[mt][nt][3] + bb.y) * alpha + rv.y;
                o = lrelu2(o, act);
                if (C) *(float2*)(C + (size_t)r1 * Nn + col) = o;
                if (Ct) *(__half2*)(Ct + (size_t)r1 * Nn + col) =
                            __floats2half2_rn(o.x, o.y);
                ssum[nt][0] += o.x; ssum[nt][1] += o.y;
                ssq[nt][0] += o.x * o.x; ssq[nt][1] += o.y * o.y;
            }
        }
    }

    if (stats_off >= 0) {
        __syncthreads();
        float* sh = (float*)dynsm;
        sh[tid] = 0.f;
        __syncthreads();
#pragma unroll
        for (int nt = 0; nt < 4; nt++) {
            int cl = wn * 32 + nt * 8 + 2 * ctg;
            atomicAdd(&sh[cl], ssum[nt][0]);
            atomicAdd(&sh[cl + 1], ssum[nt][1]);
            atomicAdd(&sh[128 + cl], ssq[nt][0]);
            atomicAdd(&sh[128 + cl + 1], ssq[nt][1]);
        }
        __syncthreads();
        atomicAdd(&g_stats[stats_off + tid], sh[tid]);
    }
}

__global__ __launch_bounds__(256, 2) void gemm_kernel(
    const __half* __restrict__ A, const __half* __restrict__ B,
    const float* __restrict__ bias, const float* __restrict__ res,
    float* __restrict__ C, __half* __restrict__ Ct,
    int M, int Nn, int K, float alpha, int act, int stats_off)
{
    gemm_body(A, B, bias, res, C, Ct, M, Nn, K, alpha, act, stats_off,
              blockIdx.y * GM, blockIdx.x * GN);
}

__global__ __launch_bounds__(256, 2) void qkv_gemm_kernel(const float* __restrict__ qb) {
    int z = blockIdx.z;
    const __half* B = g_wt + ((z == 0) ? WQ_OFF : (z == 1) ? WK_OFF : WV_OFF);
    __half* Ct = (z == 0) ? g_qh : (z == 1) ? g_kh : g_vh;
    const float* bias = (z == 0) ? qb : nullptr;
    float alpha = (z == 0) ? 0.25f : 1.0f;
    gemm_body(g_srct, B, bias, nullptr, nullptr, Ct,
              NNODES, DDIM, DDIM, alpha, 0, -1, blockIdx.y * GM, 0);
}

// ---------------- warp-per-node CSR attention aggregation -------------------
__global__ void node_agg_kernel() {
    int node = (blockIdx.x * blockDim.x + threadIdx.x) >> 5;
    if (node >= NNODES) return;
    int lane = threadIdx.x & 31;
    uint2 qa = *((const uint2*)(g_qh + (size_t)node * DDIM) + lane);
    float2 qf0 = __half22float2(*(__half2*)&qa.x);
    float2 qf1 = __half22float2(*(__half2*)&qa.y);
    float4 acc = make_float4(0.f, 0.f, 0.f, 0.f);
    float den = 0.f;
    int beg = g_rowptr[node], end = g_rowptr[node + 1];
    int i = beg;
    int esel = lane & 3;
    int gbase = lane & ~3;
    for (; i + 4 <= end; i += 4) {
        int sv = (lane < 4) ? g_csr[i + lane] : 0;
        int s[4];
#pragma unroll
        for (int j = 0; j < 4; j++) s[j] = __shfl_sync(0xffffffffu, sv, j);
        uint2 kr[4], vr[4];
#pragma unroll
        for (int j = 0; j < 4; j++)
            kr[j] = *((const uint2*)(g_kh + (size_t)s[j] * DDIM) + lane);
#pragma unroll
        for (int j = 0; j < 4; j++)
            vr[j] = *((const uint2*)(g_vh + (size_t)s[j] * DDIM) + lane);
        float p[4];
#pragma unroll
        for (int j = 0; j < 4; j++) {
            float2 k0 = __half22float2(*(__half2*)&kr[j].x);
            float2 k1 = __half22float2(*(__half2*)&kr[j].y);
            p[j] = k0.x * qf0.x + k0.y * qf0.y + k1.x * qf1.x + k1.y * qf1.y;
            p[j] += __shfl_xor_sync(0xffffffffu, p[j], 1);
            p[j] += __shfl_xor_sync(0xffffffffu, p[j], 2);
        }
        float eo = __expf(esel == 0 ? p[0] : esel == 1 ? p[1]
                          : esel == 2 ? p[2] : p[3]);
        float e[4];
#pragma unroll
        for (int j = 0; j < 4; j++)
            e[j] = __shfl_sync(0xffffffffu, eo, gbase + j);
#pragma unroll
        for (int j = 0; j < 4; j++) {
            den += e[j];
            float2 v0 = __half22float2(*(__half2*)&vr[j].x);
            float2 v1 = __half22float2(*(__half2*)&vr[j].y);
            acc.x += e[j] * v0.x; acc.y += e[j] * v0.y;
            acc.z += e[j] * v1.x; acc.w += e[j] * v1.y;
        }
    }
    for (; i < end; i++) {
        int s0 = __shfl_sync(0xffffffffu, (lane == 0) ? g_csr[i] : 0, 0);
        uint2 kr = *((const uint2*)(g_kh + (size_t)s0 * DDIM) + lane);
        uint2 vr = *((const uint2*)(g_vh + (size_t)s0 * DDIM) + lane);
        float2 k0 = __half22float2(*(__half2*)&kr.x);
        float2 k1 = __half22float2(*(__half2*)&kr.y);
        float p = k0.x * qf0.x + k0.y * qf0.y + k1.x * qf1.x + k1.y * qf1.y;
        p += __shfl_xor_sync(0xffffffffu, p, 1);
        p += __shfl_xor_sync(0xffffffffu, p, 2);
        float e0 = __expf(p);
        den += e0;
        float2 v0 = __half22float2(*(__half2*)&vr.x);
        float2 v1 = __half22float2(*(__half2*)&vr.y);
        acc.x += e0 * v0.x; acc.y += e0 * v0.y;
        acc.z += e0 * v1.x; acc.w += e0 * v1.y;
    }
    float inv = 1.f / (den + 1e-16f);
    __half2 o0 = __floats2half2_rn(acc.x * inv, acc.y * inv);
    __half2 o1 = __floats2half2_rn(acc.z * inv, acc.w * inv);
    uint2 o;
    o.x = *(unsigned*)&o0;
    o.y = *(unsigned*)&o1;
    *((uint2*)(g_aggt + (size_t)node * DDIM) + lane) = o;
}

// ---------------- BatchNorm apply (vectorized) ------------------------------
__global__ void bn_apply_kernel(const float* __restrict__ X, int off,
                                const float* __restrict__ gamma,
                                const float* __restrict__ beta,
                                float* __restrict__ Y,
                                __half* __restrict__ Yt) {
    int t = blockIdx.x * blockDim.x + threadIdx.x;
    if (t >= NSRC4) return;
    int i = t * 4;
    int j = i & (DDIM - 1);
    const float invn = 1.0f / NNODES;
    float4 x = *(const float4*)(X + i);
    float4 gm = *(const float4*)(gamma + j);
    float4 bt = *(const float4*)(beta + j);
    float4 sm = *(const float4*)(g_stats + off + j);
    float4 sq = *(const float4*)(g_stats + off + DDIM + j);
    float4 o;
    {
        float mean = sm.x * invn, var = sq.x * invn - mean * mean;
        o.x = (x.x - mean) * rsqrtf(var + EPS_BN) * gm.x + bt.x;
    }
    {
        float mean = sm.y * invn, var = sq.y * invn - mean * mean;
        o.y = (x.y - mean) * rsqrtf(var + EPS_BN) * gm.y + bt.y;
    }
    {
        float mean = sm.z * invn, var = sq.z * invn - mean * mean;
        o.z = (x.z - mean) * rsqrtf(var + EPS_BN) * gm.z + bt.z;
    }
    {
        float mean = sm.w * invn, var = sq.w * invn - mean * mean;
        o.w = (x.w - mean) * rsqrtf(var + EPS_BN) * gm.w + bt.w;
    }
    *(float4*)(Y + i) = o;
    if (Yt) {
        __half2 h0 = __floats2half2_rn(o.x, o.y);
        __half2 h1 = __floats2half2_rn(o.z, o.w);
        uint2 u;
        u.x = *(unsigned*)&h0;
        u.y = *(unsigned*)&h1;
        *(uint2*)(Yt + i) = u;
    }
}

// ---------------- launch ------------------------------------------------------
extern "C" void kernel_launch(void* const* d_in, const int* in_sizes, int n_in,
                              void* d_out, int out_size) {
    const float* src    = (const float*)d_in[0];
    const unsigned int* ei = (const unsigned int*)d_in[1];
    const float* q_w    = (const float*)d_in[2];
    const float* q_b    = (const float*)d_in[3];
    const float* k_w    = (const float*)d_in[4];
    const float* v_w    = (const float*)d_in[5];
    const float* out_w  = (const float*)d_in[6];
    const float* out_b  = (const float*)d_in[7];
    const float* g1     = (const float*)d_in[8];
    const float* b1     = (const float*)d_in[9];
    const float* lin1_w = (const float*)d_in[10];
    const float* lin1_b = (const float*)d_in[11];
    const float* lin2_w = (const float*)d_in[12];
    const float* lin2_b = (const float*)d_in[13];
    const float* g2     = (const float*)d_in[14];
    const float* b2     = (const float*)d_in[15];
    float* out = (float*)d_out;

    __half *paggt, *px1t, *pff1t, *pwt;
    float *px1, *ptmp;
    cudaGetSymbolAddress((void**)&paggt, g_aggt);
    cudaGetSymbolAddress((void**)&px1,   g_x1);
    cudaGetSymbolAddress((void**)&px1t,  g_x1t);
    cudaGetSymbolAddress((void**)&ptmp,  g_tmp);
    cudaGetSymbolAddress((void**)&pff1t, g_ff1t);
    cudaGetSymbolAddress((void**)&pwt,   g_wt);

    static cudaStream_t s1 = nullptr;
    static cudaEvent_t e0 = nullptr, e1 = nullptr;
    if (s1 == nullptr) {
        cudaStreamCreateWithFlags(&s1, cudaStreamNonBlocking);
        cudaEventCreateWithFlags(&e0, cudaEventDisableTiming);
        cudaEventCreateWithFlags(&e1, cudaEventDisableTiming);
        cudaFuncSetAttribute(gemm_kernel,
                             cudaFuncAttributeMaxDynamicSharedMemorySize, SMEMB);
        cudaFuncSetAttribute(qkv_gemm_kernel,
                             cudaFuncAttributeMaxDynamicSharedMemorySize, SMEMB);
    }

    const int MB = (NNODES + GM - 1) / GM;  // 391

    convert_kernel<<<512, 256>>>(src, q_w, k_w, v_w, out_w, lin1_w, lin2_w, ei);
    cudaEventRecord(e0, 0);

    cudaStreamWaitEvent(s1, e0, 0);
    decode_kernel<<<(ETOT + 255) / 256, 256, 0, s1>>>(ei);
    scan1_kernel<<<NCHUNK, 1024, 0, s1>>>();
    scan3_kernel<<<(NNODES + 255) / 256, 256, 0, s1>>>();
    scatter_kernel<<<(ETOT + 255) / 256, 256, 0, s1>>>();
    cudaEventRecord(e1, s1);

    qkv_gemm_kernel<<<dim3(1, MB, 3), 256, SMEMB>>>(q_b);
    cudaStreamWaitEvent(0, e1, 0);

    // attention aggregation (CSR, warp per node)
    node_agg_kernel<<<(NNODES * 32 + 255) / 256, 256>>>();

    // out projection + residual + fused BN1 stats
    gemm_kernel<<<dim3(1, MB), 256, SMEMB>>>(paggt, pwt + WO_OFF, out_b, src,
                                             ptmp, nullptr, NNODES, DDIM, DDIM,
                                             1.0f, 0, 0);

    // BN1 apply (fp32 + fp16)
    bn_apply_kernel<<<(NSRC4 + 255) / 256, 256>>>(ptmp, 0, g1, b1, px1, px1t);

    // FFN
    gemm_kernel<<<dim3(FDIM / GN, MB), 256, SMEMB>>>(px1t, pwt + W1_OFF, lin1_b,
                                                     nullptr, nullptr, pff1t,
                                                     NNODES, FDIM, DDIM,
                                                     1.0f, 1, -1);
    gemm_kernel<<<dim3(1, MB), 256, SMEMB>>>(pff1t, pwt + W2_OFF, lin2_b, px1,
                                             ptmp, nullptr, NNODES, DDIM, FDIM,
                                             1.0f, 0, 256);

    // BN2 apply -> output
    bn_apply_kernel<<<(NSRC4 + 255) / 256, 256>>>(ptmp, 256, g2, b2,
                                                  out, nullptr);
}